// round 3
// baseline (speedup 1.0000x reference)
#include <cuda_runtime.h>
#include <cstdint>

#define N_NODES   100000
#define N_EDGES   1600000
#define D         32
#define LATENT    32
#define OUT_FEAT  32

// L2-resident accumulator for segment_sum(edge_attr, receivers). 12.8 MB.
__device__ __align__(16) float g_agg[N_NODES * D];

// ---------------------------------------------------------------------------
// Kernel 1: scatter-add edge features by receiver.
// 8 threads per edge, one red.global.add.v4.f32 each (4x fewer atomic
// messages than scalar atomicAdd). Indices arrive as int32.
// ---------------------------------------------------------------------------
__global__ void scatter_kernel(const float* __restrict__ edge_attr,
                               const int* __restrict__ receivers) {
    int tid = blockIdx.x * blockDim.x + threadIdx.x;
    if (tid >= N_EDGES * 8) return;
    int e = tid >> 3;
    int c = tid & 7;

    int r = receivers[e];
    if ((unsigned)r >= N_NODES) return;

    float4 v = reinterpret_cast<const float4*>(edge_attr)[e * 8 + c];
    float* dst = g_agg + (size_t)r * D + c * 4;
    asm volatile("red.global.add.v4.f32 [%0], {%1, %2, %3, %4};"
                 :: "l"(dst), "f"(v.x), "f"(v.y), "f"(v.z), "f"(v.w)
                 : "memory");
}

// ---------------------------------------------------------------------------
// Kernel 2: fused concat + 2-layer MLP, register-tiled.
// Block = 128 threads = 128 nodes. Each thread computes a 4-node x 8-column
// tile so every shared load is amortized over 32 FFMAs (LDS:FFMA ~ 1:5.3,
// vs 1:1 in the naive one-thread-per-node version -> FFMA-bound).
//   thread: cg = tid&3 (columns 8*cg..8*cg+7), q = tid>>2 (nodes 4q..4q+3)
// x staged in shared with stride 65 (odd => scalar loads conflict-free);
// h round-trips through shared with stride 33 for layer 2.
// Global-attr + b1 layer-1 contribution is node-invariant, hoisted into gb[].
// ---------------------------------------------------------------------------
#define TPB 128
#define NB  128       // nodes per block
#define XSTR 65       // xs row stride (64 feats + 1 pad, odd)
#define HSTR 33       // ht row stride (32 + 1 pad, odd)

// dynamic shared layout (floats):
//   xs   [NB*XSTR]      = 8320
//   ht   [NB*HSTR]      = 4224
//   w1s  [64*32]        = 2048
//   w2s  [32*32]        = 1024
//   gb   [32]
//   b2s  [32]
#define SMEM_FLOATS (NB*XSTR + NB*HSTR + 2048 + 1024 + 32 + 32)

__global__ __launch_bounds__(TPB) void mlp_kernel(
    const float* __restrict__ node_attr,
    const float* __restrict__ global_attr,
    const float* __restrict__ W1, const float* __restrict__ b1,
    const float* __restrict__ W2, const float* __restrict__ b2,
    float* __restrict__ out)
{
    extern __shared__ float smem[];
    float* xs  = smem;                   // [NB][XSTR]
    float* ht  = xs  + NB * XSTR;        // [NB][HSTR]
    float* w1s = ht  + NB * HSTR;        // [64][32]
    float* w2s = w1s + 64 * 32;          // [32][32]
    float* gb  = w2s + 32 * 32;          // [32]
    float* b2s = gb + 32;                // [32]

    const int tid  = threadIdx.x;
    const int cg   = tid & 3;            // column group: cols 8*cg..8*cg+7
    const int q    = tid >> 2;           // node quad:   nodes 4q..4q+3
    const int base = blockIdx.x * NB;
    const int nvalid = min(NB, N_NODES - base);

    // Stage weights (first 64 rows of W1 only; rows 64..95 folded into gb)
    for (int i = tid; i < 64 * 32; i += TPB) w1s[i] = W1[i];
    for (int i = tid; i < 32 * 32; i += TPB) w2s[i] = W2[i];
    if (tid < 32) b2s[tid] = b2[tid];

    // gb[j] = b1[j] + sum_k global[k] * W1[64+k][j]   (coalesced W1 reads)
    if (tid < 32) {
        float acc = b1[tid];
        #pragma unroll
        for (int k = 0; k < D; k++)
            acc = fmaf(global_attr[k], W1[(64 + k) * 32 + tid], acc);
        gb[tid] = acc;
    }

    // Stage [node_attr | agg] rows, stride-65 (conflict-free writes: bank =
    // (n + k) mod 32, distinct across a warp's fixed-n k-sweep)
    for (int i = tid; i < nvalid * D; i += TPB) {
        int n = i >> 5, k = i & 31;
        xs[n * XSTR + k]      = node_attr[(base + n) * D + k];
        xs[n * XSTR + 32 + k] = g_agg[(size_t)(base + n) * D + k];
    }
    __syncthreads();

    // ---- Layer 1: h[n][c] = relu( sum_k x[n][k] * W1[k][c] + gb[c] ) ----
    float acc[4][8];
    {
        float g0[8];
        #pragma unroll
        for (int m = 0; m < 8; m++) g0[m] = gb[cg * 8 + m];
        #pragma unroll
        for (int j = 0; j < 4; j++)
            #pragma unroll
            for (int m = 0; m < 8; m++) acc[j][m] = g0[m];
    }

    const float* x0 = &xs[(4 * q + 0) * XSTR];
    const float* x1 = &xs[(4 * q + 1) * XSTR];
    const float* x2 = &xs[(4 * q + 2) * XSTR];
    const float* x3 = &xs[(4 * q + 3) * XSTR];

    #pragma unroll 4
    for (int k = 0; k < 64; k++) {
        float4 wa = *reinterpret_cast<const float4*>(&w1s[k * 32 + cg * 8]);
        float4 wb = *reinterpret_cast<const float4*>(&w1s[k * 32 + cg * 8 + 4]);
        float w[8] = {wa.x, wa.y, wa.z, wa.w, wb.x, wb.y, wb.z, wb.w};
        float xv[4] = {x0[k], x1[k], x2[k], x3[k]};
        #pragma unroll
        for (int j = 0; j < 4; j++)
            #pragma unroll
            for (int m = 0; m < 8; m++)
                acc[j][m] = fmaf(xv[j], w[m], acc[j][m]);
    }

    // relu + write h to shared (stride-33 rows)
    #pragma unroll
    for (int j = 0; j < 4; j++) {
        int n = 4 * q + j;
        #pragma unroll
        for (int m = 0; m < 8; m++)
            ht[n * HSTR + cg * 8 + m] = fmaxf(acc[j][m], 0.f);
    }
    __syncthreads();

    // ---- Layer 2: o[n][c] = sum_i h[n][i] * W2[i][c] + b2[c] ----
    float o[4][8];
    {
        float bb[8];
        #pragma unroll
        for (int m = 0; m < 8; m++) bb[m] = b2s[cg * 8 + m];
        #pragma unroll
        for (int j = 0; j < 4; j++)
            #pragma unroll
            for (int m = 0; m < 8; m++) o[j][m] = bb[m];
    }

    const float* h0 = &ht[(4 * q + 0) * HSTR];
    const float* h1 = &ht[(4 * q + 1) * HSTR];
    const float* h2 = &ht[(4 * q + 2) * HSTR];
    const float* h3 = &ht[(4 * q + 3) * HSTR];

    #pragma unroll 4
    for (int i = 0; i < 32; i++) {
        float4 wa = *reinterpret_cast<const float4*>(&w2s[i * 32 + cg * 8]);
        float4 wb = *reinterpret_cast<const float4*>(&w2s[i * 32 + cg * 8 + 4]);
        float w[8] = {wa.x, wa.y, wa.z, wa.w, wb.x, wb.y, wb.z, wb.w};
        float hv[4] = {h0[i], h1[i], h2[i], h3[i]};
        #pragma unroll
        for (int j = 0; j < 4; j++)
            #pragma unroll
            for (int m = 0; m < 8; m++)
                o[j][m] = fmaf(hv[j], w[m], o[j][m]);
    }

    // Store: two float4 per node (cols 8cg..8cg+7)
    #pragma unroll
    for (int j = 0; j < 4; j++) {
        int n = 4 * q + j;
        if (n < nvalid) {
            float* dst = out + (size_t)(base + n) * OUT_FEAT + cg * 8;
            reinterpret_cast<float4*>(dst)[0] =
                make_float4(o[j][0], o[j][1], o[j][2], o[j][3]);
            reinterpret_cast<float4*>(dst)[1] =
                make_float4(o[j][4], o[j][5], o[j][6], o[j][7]);
        }
    }
}

// ---------------------------------------------------------------------------
// Launch. Inputs: node_attr, edge_index (int32 on device), edge_attr,
// global_attr, W1, b1, W2, b2. Output: float32 [100000, 32].
// ---------------------------------------------------------------------------
extern "C" void kernel_launch(void* const* d_in, const int* in_sizes, int n_in,
                              void* d_out, int out_size) {
    const float* node_attr   = (const float*)d_in[0];
    const int*   edge_index  = (const int*)d_in[1];
    const float* edge_attr   = (const float*)d_in[2];
    const float* global_attr = (const float*)d_in[3];
    const float* W1          = (const float*)d_in[4];
    const float* b1          = (const float*)d_in[5];
    const float* W2          = (const float*)d_in[6];
    const float* b2          = (const float*)d_in[7];
    float*       out         = (float*)d_out;

    const int* receivers = edge_index + N_EDGES;

    // 1) zero accumulator via graph memset node
    void* agg_ptr = nullptr;
    cudaGetSymbolAddress(&agg_ptr, g_agg);
    cudaMemsetAsync(agg_ptr, 0, (size_t)N_NODES * D * sizeof(float));

    // 2) scatter-add edges
    {
        int n = N_EDGES * 8;
        scatter_kernel<<<(n + 255) / 256, 256>>>(edge_attr, receivers);
    }

    // 3) fused concat + MLP (dynamic smem > 48KB)
    {
        size_t smem_bytes = SMEM_FLOATS * sizeof(float);
        cudaFuncSetAttribute(mlp_kernel,
                             cudaFuncAttributeMaxDynamicSharedMemorySize,
                             (int)smem_bytes);
        int blocks = (N_NODES + NB - 1) / NB;
        mlp_kernel<<<blocks, TPB, smem_bytes>>>(node_attr, global_attr,
                                                W1, b1, W2, b2, out);
    }
    (void)in_sizes; (void)n_in; (void)out_size;
}

// round 4
// speedup vs baseline: 1.1910x; 1.1910x over previous
#include <cuda_runtime.h>
#include <cstdint>

#define N_NODES   100000
#define N_EDGES   1600000
#define D         32
#define OUT_FEAT  32

// L2-resident accumulator for segment_sum(edge_attr, receivers). 12.8 MB.
__device__ __align__(16) float g_agg[N_NODES * D];

// ---------------------------------------------------------------------------
// Kernel 1: scatter-add edge features by receiver.
// 8 threads per edge, one red.global.add.v4.f32 each. Coalesced 128B reads.
// ---------------------------------------------------------------------------
__global__ void scatter_kernel(const float* __restrict__ edge_attr,
                               const int* __restrict__ receivers) {
    int tid = blockIdx.x * blockDim.x + threadIdx.x;
    if (tid >= N_EDGES * 8) return;
    int e = tid >> 3;
    int c = tid & 7;

    int r = receivers[e];
    if ((unsigned)r >= N_NODES) return;

    float4 v = reinterpret_cast<const float4*>(edge_attr)[e * 8 + c];
    float* dst = g_agg + (size_t)r * D + c * 4;
    asm volatile("red.global.add.v4.f32 [%0], {%1, %2, %3, %4};"
                 :: "l"(dst), "f"(v.x), "f"(v.y), "f"(v.z), "f"(v.w)
                 : "memory");
}

// ---------------------------------------------------------------------------
// Kernel 2: fused concat + 2-layer MLP, register-tiled 4 nodes x 8 cols.
// Fixes vs last round:
//  - ht aliased into xs region (write-after-read fenced by syncthreads):
//    smem 62.7KB -> 45.8KB -> 4 blocks/SM (16 warps, was 12).
//  - staging fully unrolled, 16 independent LDG.128 per thread (MLP~16)
//    instead of a serialized scalar loop (DRAM latency exposed ~16x less).
// ---------------------------------------------------------------------------
#define TPB 128
#define NB  128
#define XSTR 65     // xs row stride (odd => conflict-free scalar access)
#define HSTR 33     // ht row stride (odd)

// smem floats: xs (ht aliased inside) + w1s + w2s + gb + b2
#define SMEM_FLOATS (NB*XSTR + 64*32 + 32*32 + 32 + 32)

__global__ __launch_bounds__(TPB) void mlp_kernel(
    const float* __restrict__ node_attr,
    const float* __restrict__ global_attr,
    const float* __restrict__ W1, const float* __restrict__ b1,
    const float* __restrict__ W2, const float* __restrict__ b2,
    float* __restrict__ out)
{
    extern __shared__ float smem[];
    float* xs  = smem;                   // [NB][XSTR]; later reused as ht[NB][HSTR]
    float* w1s = xs  + NB * XSTR;        // [64][32]
    float* w2s = w1s + 64 * 32;          // [32][32]
    float* gb  = w2s + 32 * 32;          // [32]
    float* b2s = gb + 32;                // [32]

    const int tid  = threadIdx.x;
    const int cg   = tid & 3;            // column group: cols 8*cg..8*cg+7
    const int q    = tid >> 2;           // node quad:   nodes 4q..4q+3
    const int base = blockIdx.x * NB;
    const int nvalid = min(NB, N_NODES - base);
    const bool full = (nvalid == NB);

    // ---- Stage weights: 4+2 LDG.128 per thread, independent ----
    {
        const float4* w1v = reinterpret_cast<const float4*>(W1);
        const float4* w2v = reinterpret_cast<const float4*>(W2);
        float4 a0 = w1v[tid];
        float4 a1 = w1v[tid + 128];
        float4 a2 = w1v[tid + 256];
        float4 a3 = w1v[tid + 384];
        float4 c0 = w2v[tid];
        float4 c1 = w2v[tid + 128];
        reinterpret_cast<float4*>(w1s)[tid]       = a0;
        reinterpret_cast<float4*>(w1s)[tid + 128] = a1;
        reinterpret_cast<float4*>(w1s)[tid + 256] = a2;
        reinterpret_cast<float4*>(w1s)[tid + 384] = a3;
        reinterpret_cast<float4*>(w2s)[tid]       = c0;
        reinterpret_cast<float4*>(w2s)[tid + 128] = c1;
    }
    if (tid < 32) b2s[tid] = b2[tid];

    // gb[j] = b1[j] + sum_k global[k]*W1[64+k][j]  (coalesced, fully unrolled)
    if (tid < 32) {
        float acc = b1[tid];
        #pragma unroll
        for (int k = 0; k < D; k++)
            acc = fmaf(global_attr[k], W1[(64 + k) * 32 + tid], acc);
        gb[tid] = acc;
    }

    // ---- Stage x = [node_attr | agg]: 8+8 LDG.128, all independent ----
    // chunk t: f4 index idx = tid + 128*t -> n = idx>>3, c = idx&7
    {
        float4 va[8], vb[8];
        const float4* nav = reinterpret_cast<const float4*>(node_attr) + (size_t)base * 8;
        const float4* agv = reinterpret_cast<const float4*>(g_agg)     + (size_t)base * 8;
        if (full) {
            #pragma unroll
            for (int t = 0; t < 8; t++) va[t] = nav[tid + 128 * t];
            #pragma unroll
            for (int t = 0; t < 8; t++) vb[t] = agv[tid + 128 * t];
        } else {
            #pragma unroll
            for (int t = 0; t < 8; t++) {
                int idx = tid + 128 * t;
                if ((idx >> 3) < nvalid) { va[t] = nav[idx]; vb[t] = agv[idx]; }
                else { va[t] = make_float4(0,0,0,0); vb[t] = make_float4(0,0,0,0); }
            }
        }
        #pragma unroll
        for (int t = 0; t < 8; t++) {
            int idx = tid + 128 * t;
            int n = idx >> 3, c = idx & 7;
            float* p = &xs[n * XSTR + 4 * c];
            p[0] = va[t].x; p[1] = va[t].y; p[2] = va[t].z; p[3] = va[t].w;
            float* pb = p + 32;
            pb[0] = vb[t].x; pb[1] = vb[t].y; pb[2] = vb[t].z; pb[3] = vb[t].w;
        }
    }
    __syncthreads();

    // ---- Layer 1: acc[j][m] = gb + sum_k x[4q+j][k] * W1[k][8cg+m] ----
    float acc[4][8];
    #pragma unroll
    for (int j = 0; j < 4; j++)
        #pragma unroll
        for (int m = 0; m < 8; m++) acc[j][m] = gb[cg * 8 + m];

    const float* x0 = &xs[(4 * q + 0) * XSTR];
    const float* x1 = &xs[(4 * q + 1) * XSTR];
    const float* x2 = &xs[(4 * q + 2) * XSTR];
    const float* x3 = &xs[(4 * q + 3) * XSTR];

    #pragma unroll 4
    for (int k = 0; k < 64; k++) {
        float4 wa = *reinterpret_cast<const float4*>(&w1s[k * 32 + cg * 8]);
        float4 wb = *reinterpret_cast<const float4*>(&w1s[k * 32 + cg * 8 + 4]);
        float w[8] = {wa.x, wa.y, wa.z, wa.w, wb.x, wb.y, wb.z, wb.w};
        float xv[4] = {x0[k], x1[k], x2[k], x3[k]};
        #pragma unroll
        for (int j = 0; j < 4; j++)
            #pragma unroll
            for (int m = 0; m < 8; m++)
                acc[j][m] = fmaf(xv[j], w[m], acc[j][m]);
    }

    // ---- relu + round-trip h through smem (reusing xs region) ----
    __syncthreads();   // everyone done READING xs
    float* ht = xs;    // [NB][HSTR], 4224 floats < NB*XSTR
    #pragma unroll
    for (int j = 0; j < 4; j++) {
        int n = 4 * q + j;
        #pragma unroll
        for (int m = 0; m < 8; m++)
            ht[n * HSTR + cg * 8 + m] = fmaxf(acc[j][m], 0.f);
    }
    __syncthreads();

    // ---- Layer 2: o = h @ W2 + b2 ----
    float o[4][8];
    #pragma unroll
    for (int j = 0; j < 4; j++)
        #pragma unroll
        for (int m = 0; m < 8; m++) o[j][m] = b2s[cg * 8 + m];

    const float* h0 = &ht[(4 * q + 0) * HSTR];
    const float* h1 = &ht[(4 * q + 1) * HSTR];
    const float* h2 = &ht[(4 * q + 2) * HSTR];
    const float* h3 = &ht[(4 * q + 3) * HSTR];

    #pragma unroll 4
    for (int i = 0; i < 32; i++) {
        float4 wa = *reinterpret_cast<const float4*>(&w2s[i * 32 + cg * 8]);
        float4 wb = *reinterpret_cast<const float4*>(&w2s[i * 32 + cg * 8 + 4]);
        float w[8] = {wa.x, wa.y, wa.z, wa.w, wb.x, wb.y, wb.z, wb.w};
        float hv[4] = {h0[i], h1[i], h2[i], h3[i]};
        #pragma unroll
        for (int j = 0; j < 4; j++)
            #pragma unroll
            for (int m = 0; m < 8; m++)
                o[j][m] = fmaf(hv[j], w[m], o[j][m]);
    }

    // ---- Store: two float4 per node row-chunk ----
    #pragma unroll
    for (int j = 0; j < 4; j++) {
        int n = 4 * q + j;
        if (n < nvalid) {
            float* dst = out + (size_t)(base + n) * OUT_FEAT + cg * 8;
            reinterpret_cast<float4*>(dst)[0] =
                make_float4(o[j][0], o[j][1], o[j][2], o[j][3]);
            reinterpret_cast<float4*>(dst)[1] =
                make_float4(o[j][4], o[j][5], o[j][6], o[j][7]);
        }
    }
}

// ---------------------------------------------------------------------------
// Launch.
// ---------------------------------------------------------------------------
extern "C" void kernel_launch(void* const* d_in, const int* in_sizes, int n_in,
                              void* d_out, int out_size) {
    const float* node_attr   = (const float*)d_in[0];
    const int*   edge_index  = (const int*)d_in[1];
    const float* edge_attr   = (const float*)d_in[2];
    const float* global_attr = (const float*)d_in[3];
    const float* W1          = (const float*)d_in[4];
    const float* b1          = (const float*)d_in[5];
    const float* W2          = (const float*)d_in[6];
    const float* b2          = (const float*)d_in[7];
    float*       out         = (float*)d_out;

    const int* receivers = edge_index + N_EDGES;

    // 1) zero accumulator (graph memset node)
    void* agg_ptr = nullptr;
    cudaGetSymbolAddress(&agg_ptr, g_agg);
    cudaMemsetAsync(agg_ptr, 0, (size_t)N_NODES * D * sizeof(float));

    // 2) scatter-add edges
    {
        int n = N_EDGES * 8;
        scatter_kernel<<<(n + 255) / 256, 256>>>(edge_attr, receivers);
    }

    // 3) fused concat + MLP
    {
        size_t smem_bytes = SMEM_FLOATS * sizeof(float);
        cudaFuncSetAttribute(mlp_kernel,
                             cudaFuncAttributeMaxDynamicSharedMemorySize,
                             (int)smem_bytes);
        int blocks = (N_NODES + NB - 1) / NB;
        mlp_kernel<<<blocks, TPB, smem_bytes>>>(node_attr, global_attr,
                                                W1, b1, W2, b2, out);
    }
    (void)in_sizes; (void)n_in; (void)out_size;
}

// round 5
// speedup vs baseline: 1.2230x; 1.0268x over previous
#include <cuda_runtime.h>
#include <cstdint>

#define N_NODES   100000
#define N_EDGES   1600000
#define D         32
#define OUT_FEAT  32

// L2-resident scratch (device globals: no allocation allowed in kernel_launch)
__device__ __align__(16) float g_agg[N_NODES * D];       // segment_sum result
__device__ __align__(16) float g_partial[N_NODES * D];   // node@W1[0:32] + gb

#define TPB  128
#define NB   128
#define XSTR 33

#define P_BLOCKS     782                    // ceil(100000 / 128)
#define S_LANES      (N_EDGES * 8)          // 12.8M float4 lanes
#define S_PER_BLOCK  1024                   // 128 threads x 8 lanes
#define S_BLOCKS     (S_LANES / S_PER_BLOCK)  // 12500 exactly

// fused kernel smem (partial path): xs[128][33] + w1a[32][32] + gb[32]
#define SMEM1_FLOATS (NB * XSTR + 32 * 32 + 32)
// final kernel smem: xs/ht[128][33] + w1b[32][32] + w2[32][32] + b2[32]
#define SMEM2_FLOATS (NB * XSTR + 32 * 32 + 32 * 32 + 32)

// ---------------------------------------------------------------------------
// Kernel A (fused grid): blocks [0, P_BLOCKS) compute the scatter-independent
// partial MLP term P = node_attr @ W1[0:32] + (b1 + global @ W1[64:96]);
// blocks [P_BLOCKS, ...) do the edge scatter-add (L2-bound red.v4). The
// partial work hides entirely under the scatter's L2-RMW bottleneck.
// ---------------------------------------------------------------------------
__global__ __launch_bounds__(TPB) void fused_partial_scatter(
    const float* __restrict__ edge_attr,
    const int* __restrict__ receivers,
    const float* __restrict__ node_attr,
    const float* __restrict__ global_attr,
    const float* __restrict__ W1,
    const float* __restrict__ b1)
{
    const int tid = threadIdx.x;

    if (blockIdx.x >= P_BLOCKS) {
        // ---------------- scatter path: 8 independent lanes/thread ----------
        const int lane0 = (blockIdx.x - P_BLOCKS) * S_PER_BLOCK + tid;
        float4 v[8];
        int    r[8];
        #pragma unroll
        for (int t = 0; t < 8; t++) {
            int lane = lane0 + 128 * t;
            r[t] = receivers[lane >> 3];
            v[t] = reinterpret_cast<const float4*>(edge_attr)[lane];
        }
        #pragma unroll
        for (int t = 0; t < 8; t++) {
            int lane = lane0 + 128 * t;
            int c = lane & 7;
            if ((unsigned)r[t] < N_NODES) {
                float* dst = g_agg + (size_t)r[t] * D + c * 4;
                asm volatile("red.global.add.v4.f32 [%0], {%1, %2, %3, %4};"
                             :: "l"(dst), "f"(v[t].x), "f"(v[t].y),
                                "f"(v[t].z), "f"(v[t].w)
                             : "memory");
            }
        }
        return;
    }

    // ---------------- partial-MLP path ------------------------------------
    extern __shared__ float smem[];
    float* xs  = smem;                 // [NB][XSTR] node features
    float* w1s = xs + NB * XSTR;       // [32][32]  W1 rows 0..31
    float* gb  = w1s + 32 * 32;        // [32]

    const int cg   = tid & 3;
    const int q    = tid >> 2;
    const int base = blockIdx.x * NB;
    const int nvalid = min(NB, N_NODES - base);
    const bool full  = (nvalid == NB);

    // stage W1 rows 0..31 (1024 floats = 256 f4)
    {
        const float4* w1v = reinterpret_cast<const float4*>(W1);
        float4 a0 = w1v[tid], a1 = w1v[tid + 128];
        reinterpret_cast<float4*>(w1s)[tid]       = a0;
        reinterpret_cast<float4*>(w1s)[tid + 128] = a1;
    }
    // gb[j] = b1[j] + sum_k global[k] * W1[64+k][j]
    if (tid < 32) {
        float acc = b1[tid];
        #pragma unroll
        for (int k = 0; k < D; k++)
            acc = fmaf(global_attr[k], W1[(64 + k) * 32 + tid], acc);
        gb[tid] = acc;
    }
    // stage node rows: 1024 f4, 8 per thread, independent
    {
        const float4* nav = reinterpret_cast<const float4*>(node_attr) + (size_t)base * 8;
        float4 va[8];
        #pragma unroll
        for (int t = 0; t < 8; t++) {
            int idx = tid + 128 * t;
            if (full || (idx >> 3) < nvalid) va[t] = nav[idx];
            else va[t] = make_float4(0, 0, 0, 0);
        }
        #pragma unroll
        for (int t = 0; t < 8; t++) {
            int idx = tid + 128 * t;
            int n = idx >> 3, c = idx & 7;
            float* p = &xs[n * XSTR + 4 * c];
            p[0] = va[t].x; p[1] = va[t].y; p[2] = va[t].z; p[3] = va[t].w;
        }
    }
    __syncthreads();

    float acc[4][8];
    #pragma unroll
    for (int j = 0; j < 4; j++)
        #pragma unroll
        for (int m = 0; m < 8; m++) acc[j][m] = gb[cg * 8 + m];

    const float* x0 = &xs[(4 * q + 0) * XSTR];
    const float* x1 = &xs[(4 * q + 1) * XSTR];
    const float* x2 = &xs[(4 * q + 2) * XSTR];
    const float* x3 = &xs[(4 * q + 3) * XSTR];

    #pragma unroll 4
    for (int k = 0; k < 32; k++) {
        float4 wa = *reinterpret_cast<const float4*>(&w1s[k * 32 + cg * 8]);
        float4 wb = *reinterpret_cast<const float4*>(&w1s[k * 32 + cg * 8 + 4]);
        float w[8] = {wa.x, wa.y, wa.z, wa.w, wb.x, wb.y, wb.z, wb.w};
        float xv[4] = {x0[k], x1[k], x2[k], x3[k]};
        #pragma unroll
        for (int j = 0; j < 4; j++)
            #pragma unroll
            for (int m = 0; m < 8; m++)
                acc[j][m] = fmaf(xv[j], w[m], acc[j][m]);
    }

    // write P (no relu yet)
    #pragma unroll
    for (int j = 0; j < 4; j++) {
        int n = 4 * q + j;
        if (n < nvalid) {
            float* dst = g_partial + (size_t)(base + n) * D + cg * 8;
            reinterpret_cast<float4*>(dst)[0] =
                make_float4(acc[j][0], acc[j][1], acc[j][2], acc[j][3]);
            reinterpret_cast<float4*>(dst)[1] =
                make_float4(acc[j][4], acc[j][5], acc[j][6], acc[j][7]);
        }
    }
}

// ---------------------------------------------------------------------------
// Kernel B: final = relu(P + agg @ W1[32:64]) @ W2 + b2.
// Only 32 k-iterations in layer 1; smem 25.2KB -> ~7 blocks/SM (28 warps).
// ---------------------------------------------------------------------------
__global__ __launch_bounds__(TPB) void final_kernel(
    const float* __restrict__ W1,
    const float* __restrict__ W2, const float* __restrict__ b2,
    float* __restrict__ out)
{
    extern __shared__ float smem[];
    float* xs  = smem;                 // [NB][XSTR] agg features; reused as ht
    float* w1s = xs + NB * XSTR;       // [32][32]  W1 rows 32..63
    float* w2s = w1s + 32 * 32;        // [32][32]
    float* b2s = w2s + 32 * 32;        // [32]

    const int tid  = threadIdx.x;
    const int cg   = tid & 3;
    const int q    = tid >> 2;
    const int base = blockIdx.x * NB;
    const int nvalid = min(NB, N_NODES - base);
    const bool full  = (nvalid == NB);

    // stage W1 rows 32..63 (f4 offset 256) and W2
    {
        const float4* w1v = reinterpret_cast<const float4*>(W1);
        const float4* w2v = reinterpret_cast<const float4*>(W2);
        float4 a0 = w1v[256 + tid], a1 = w1v[256 + tid + 128];
        float4 c0 = w2v[tid],       c1 = w2v[tid + 128];
        reinterpret_cast<float4*>(w1s)[tid]       = a0;
        reinterpret_cast<float4*>(w1s)[tid + 128] = a1;
        reinterpret_cast<float4*>(w2s)[tid]       = c0;
        reinterpret_cast<float4*>(w2s)[tid + 128] = c1;
    }
    if (tid < 32) b2s[tid] = b2[tid];

    // stage agg rows (L2-hot), 8 f4/thread
    {
        const float4* agv = reinterpret_cast<const float4*>(g_agg) + (size_t)base * 8;
        float4 vb[8];
        #pragma unroll
        for (int t = 0; t < 8; t++) {
            int idx = tid + 128 * t;
            if (full || (idx >> 3) < nvalid) vb[t] = agv[idx];
            else vb[t] = make_float4(0, 0, 0, 0);
        }
        #pragma unroll
        for (int t = 0; t < 8; t++) {
            int idx = tid + 128 * t;
            int n = idx >> 3, c = idx & 7;
            float* p = &xs[n * XSTR + 4 * c];
            p[0] = vb[t].x; p[1] = vb[t].y; p[2] = vb[t].z; p[3] = vb[t].w;
        }
    }

    // load this thread's P tile directly from global (coalesced 32B sectors)
    float acc[4][8];
    {
        const float4* pv = reinterpret_cast<const float4*>(g_partial) + (size_t)base * 8;
        #pragma unroll
        for (int j = 0; j < 4; j++) {
            int n = 4 * q + j;
            float4 pa, pb;
            if (full || n < nvalid) {
                pa = pv[n * 8 + cg * 2];
                pb = pv[n * 8 + cg * 2 + 1];
            } else { pa = make_float4(0,0,0,0); pb = pa; }
            acc[j][0] = pa.x; acc[j][1] = pa.y; acc[j][2] = pa.z; acc[j][3] = pa.w;
            acc[j][4] = pb.x; acc[j][5] = pb.y; acc[j][6] = pb.z; acc[j][7] = pb.w;
        }
    }
    __syncthreads();

    // layer 1 remainder: += agg @ W1[32:64]
    const float* x0 = &xs[(4 * q + 0) * XSTR];
    const float* x1 = &xs[(4 * q + 1) * XSTR];
    const float* x2 = &xs[(4 * q + 2) * XSTR];
    const float* x3 = &xs[(4 * q + 3) * XSTR];

    #pragma unroll 4
    for (int k = 0; k < 32; k++) {
        float4 wa = *reinterpret_cast<const float4*>(&w1s[k * 32 + cg * 8]);
        float4 wb = *reinterpret_cast<const float4*>(&w1s[k * 32 + cg * 8 + 4]);
        float w[8] = {wa.x, wa.y, wa.z, wa.w, wb.x, wb.y, wb.z, wb.w};
        float xv[4] = {x0[k], x1[k], x2[k], x3[k]};
        #pragma unroll
        for (int j = 0; j < 4; j++)
            #pragma unroll
            for (int m = 0; m < 8; m++)
                acc[j][m] = fmaf(xv[j], w[m], acc[j][m]);
    }

    // relu + round-trip h through smem (reuse xs region, same size)
    __syncthreads();
    float* ht = xs;   // [NB][XSTR]
    #pragma unroll
    for (int j = 0; j < 4; j++) {
        int n = 4 * q + j;
        #pragma unroll
        for (int m = 0; m < 8; m++)
            ht[n * XSTR + cg * 8 + m] = fmaxf(acc[j][m], 0.f);
    }
    __syncthreads();

    // layer 2
    float o[4][8];
    #pragma unroll
    for (int j = 0; j < 4; j++)
        #pragma unroll
        for (int m = 0; m < 8; m++) o[j][m] = b2s[cg * 8 + m];

    const float* h0 = &ht[(4 * q + 0) * XSTR];
    const float* h1 = &ht[(4 * q + 1) * XSTR];
    const float* h2 = &ht[(4 * q + 2) * XSTR];
    const float* h3 = &ht[(4 * q + 3) * XSTR];

    #pragma unroll 4
    for (int i = 0; i < 32; i++) {
        float4 wa = *reinterpret_cast<const float4*>(&w2s[i * 32 + cg * 8]);
        float4 wb = *reinterpret_cast<const float4*>(&w2s[i * 32 + cg * 8 + 4]);
        float w[8] = {wa.x, wa.y, wa.z, wa.w, wb.x, wb.y, wb.z, wb.w};
        float hv[4] = {h0[i], h1[i], h2[i], h3[i]};
        #pragma unroll
        for (int j = 0; j < 4; j++)
            #pragma unroll
            for (int m = 0; m < 8; m++)
                o[j][m] = fmaf(hv[j], w[m], o[j][m]);
    }

    #pragma unroll
    for (int j = 0; j < 4; j++) {
        int n = 4 * q + j;
        if (n < nvalid) {
            float* dst = out + (size_t)(base + n) * OUT_FEAT + cg * 8;
            reinterpret_cast<float4*>(dst)[0] =
                make_float4(o[j][0], o[j][1], o[j][2], o[j][3]);
            reinterpret_cast<float4*>(dst)[1] =
                make_float4(o[j][4], o[j][5], o[j][6], o[j][7]);
        }
    }
}

// ---------------------------------------------------------------------------
// Launch.
// ---------------------------------------------------------------------------
extern "C" void kernel_launch(void* const* d_in, const int* in_sizes, int n_in,
                              void* d_out, int out_size) {
    const float* node_attr   = (const float*)d_in[0];
    const int*   edge_index  = (const int*)d_in[1];
    const float* edge_attr   = (const float*)d_in[2];
    const float* global_attr = (const float*)d_in[3];
    const float* W1          = (const float*)d_in[4];
    const float* b1          = (const float*)d_in[5];
    const float* W2          = (const float*)d_in[6];
    const float* b2          = (const float*)d_in[7];
    float*       out         = (float*)d_out;

    const int* receivers = edge_index + N_EDGES;

    // 1) zero accumulator (graph memset node)
    void* agg_ptr = nullptr;
    cudaGetSymbolAddress(&agg_ptr, g_agg);
    cudaMemsetAsync(agg_ptr, 0, (size_t)N_NODES * D * sizeof(float));

    // 2) fused partial-MLP + scatter (partial blocks first => wave-1 resident)
    {
        size_t smem1 = SMEM1_FLOATS * sizeof(float);
        cudaFuncSetAttribute(fused_partial_scatter,
                             cudaFuncAttributeMaxDynamicSharedMemorySize,
                             (int)smem1);
        fused_partial_scatter<<<P_BLOCKS + S_BLOCKS, TPB, smem1>>>(
            edge_attr, receivers, node_attr, global_attr, W1, b1);
    }

    // 3) final: relu(P + agg@W1b) @ W2 + b2
    {
        size_t smem2 = SMEM2_FLOATS * sizeof(float);
        cudaFuncSetAttribute(final_kernel,
                             cudaFuncAttributeMaxDynamicSharedMemorySize,
                             (int)smem2);
        final_kernel<<<P_BLOCKS, TPB, smem2>>>(W1, W2, b2, out);
    }
    (void)in_sizes; (void)n_in; (void)out_size;
}